// round 2
// baseline (speedup 1.0000x reference)
#include <cuda_runtime.h>

typedef unsigned long long ull;

#define NMAX 25000
#define BN 8
#define TILE 64

__device__ float g_q[NMAX * 224];
__device__ float g_k[NMAX * 224];
__device__ float g_v[NMAX * 224];

__device__ __forceinline__ float silu_f(float x) { return x / (1.0f + __expf(-x)); }

__device__ __forceinline__ ull fpack2(float lo, float hi) {
    ull u; asm("mov.b64 %0,{%1,%2};" : "=l"(u) : "f"(lo), "f"(hi)); return u;
}
__device__ __forceinline__ void funpack2(ull u, float& lo, float& hi) {
    asm("mov.b64 {%0,%1},%2;" : "=f"(lo), "=f"(hi) : "l"(u));
}
__device__ __forceinline__ void ffma2(ull& d, ull a, ull b) {
    asm("fma.rn.f32x2 %0, %1, %2, %0;" : "+l"(d) : "l"(a), "l"(b));
}

// ---------------------------------------------------------------------------
__global__ void k_zero(float* out, int n) {
    int i = blockIdx.x * blockDim.x + threadIdx.x;
    int st = gridDim.x * blockDim.x;
    for (; i < n; i += st) out[i] = 0.0f;
}

// ---------------------------------------------------------------------------
// q = silu(Wq x), k = silu(Wk x), v = Wv x    (per node)
// smem: WqT[7][32j][32i] | WkT same | WvT[4][56j *57][56i] | xs[8][224]
__global__ void __launch_bounds__(256, 1) k_node(
    const float* __restrict__ x,
    const float* __restrict__ Wq, const float* __restrict__ Wk,
    const float* __restrict__ Wv, int N)
{
    extern __shared__ float sm[];
    float* WqT = sm;                // 7168
    float* WkT = sm + 7168;         // 7168
    float* WvT = sm + 14336;        // 12768 (stride 57 rows)
    float* xs  = sm + 27104;        // 1792

    int tid = threadIdx.x;
    for (int idx = tid; idx < 7168; idx += 256) {
        int h = idx >> 10, r = idx & 1023, i = r >> 5, j = r & 31;
        WqT[h * 1024 + j * 32 + i] = Wq[idx];
        WkT[h * 1024 + j * 32 + i] = Wk[idx];
    }
    for (int idx = tid; idx < 12544; idx += 256) {
        int h = idx / 3136, r = idx - h * 3136, i = r / 56, j = r - i * 56;
        WvT[h * 3192 + j * 57 + i] = Wv[idx];
    }
    int nb0 = blockIdx.x * BN;
    int cnt = N - nb0; if (cnt > BN) cnt = BN; if (cnt < 0) cnt = 0;
    for (int idx = tid; idx < BN * 224; idx += 256) {
        int u = idx / 224, f = idx - u * 224;
        xs[idx] = (u < cnt) ? x[(nb0 + u) * 224 + f] : 0.0f;
    }
    __syncthreads();

    if (tid < 224) {
        int h = tid >> 5, iq = tid & 31;
        int hv = tid / 56, iv = tid - hv * 56;
        float aq[BN], ak[BN], av[BN];
#pragma unroll
        for (int u = 0; u < BN; u++) { aq[u] = 0.f; ak[u] = 0.f; av[u] = 0.f; }
#pragma unroll 4
        for (int j = 0; j < 32; j++) {
            float wq = WqT[h * 1024 + j * 32 + iq];
            float wk = WkT[h * 1024 + j * 32 + iq];
#pragma unroll
            for (int u = 0; u < BN; u++) {
                float xv = xs[u * 224 + h * 32 + j];
                aq[u] += wq * xv; ak[u] += wk * xv;
            }
        }
#pragma unroll 4
        for (int j = 0; j < 56; j++) {
            float wv = WvT[hv * 3192 + j * 57 + iv];
#pragma unroll
            for (int u = 0; u < BN; u++) av[u] += wv * xs[u * 224 + hv * 56 + j];
        }
        for (int u = 0; u < cnt; u++) {
            g_q[(nb0 + u) * 224 + tid] = silu_f(aq[u]);
            g_k[(nb0 + u) * 224 + tid] = silu_f(ak[u]);
            g_v[(nb0 + u) * 224 + tid] = av[u];
        }
    }
}

// ---------------------------------------------------------------------------
// Fused edge kernel: hidden MLP -> 224x224 GEMM (f32x2) -> alpha -> scatter
__global__ void __launch_bounds__(256, 2) k_edge(
    const float* __restrict__ ev, const float* __restrict__ rbf,
    const float* __restrict__ ylm, const float* __restrict__ cut,
    const int* __restrict__ idx_i, const int* __restrict__ idx_j,
    const float* __restrict__ W1r, const float* __restrict__ b1r,
    const float* __restrict__ W2r, const float* __restrict__ b2r,
    const float* __restrict__ W1s, const float* __restrict__ b1s,
    const float* __restrict__ W2s, const float* __restrict__ b2s,
    float* __restrict__ outx, float* __restrict__ outev, int P)
{
    extern __shared__ float sm[];
    float* act_s  = sm;                  // 224*66 = 14784 (k-major, stride 66)
    float* w2_s   = sm + 14784;          // 16*224 = 3584
    float* w1r_s  = sm + 18368;          // 3584
    float* rbfc_s = sm + 21952;          // 64*32 = 2048
    float* tmp_s  = sm + 24000;          // 64*15 = 960
    float* l0_s   = sm + 24960;          // 64*3 = 192
    float* w1s_s  = sm + 25152;          // 336
    float* alph_s = sm + 25488;          // 64*7 = 448
    float* cut_s  = sm + 25936;          // 64
    int*   sI     = (int*)(sm + 26000);  // 64
    int*   sJ     = (int*)(sm + 26064);  // 64  -> total 26128 floats

    int tid = threadIdx.x, tx = tid & 31, ty = tid >> 5;
    int p0 = blockIdx.x * TILE;

    for (int idx = tid; idx < 3584; idx += 256) w1r_s[idx] = W1r[idx];
    for (int idx = tid; idx < 336; idx += 256) w1s_s[idx] = W1s[idx];
    for (int idx = tid; idx < TILE; idx += 256) {
        int p = p0 + idx; bool v = p < P;
        sI[idx] = v ? idx_i[p] : 0;
        sJ[idx] = v ? idx_j[p] : 0;
        cut_s[idx] = v ? cut[p] : 0.f;
    }
    __syncthreads();
    for (int idx = tid; idx < 2048; idx += 256) {
        int e = idx >> 5, j = idx & 31; int p = p0 + e;
        rbfc_s[idx] = (p < P) ? rbf[p * 32 + j] * cut_s[e] : 0.f;
    }
    for (int idx = tid; idx < 960; idx += 256) {
        int e = idx / 15, o = idx - e * 15; int p = p0 + e;
        float d = 0.f;
        if (p < P) d = ev[sJ[e] * 15 + o] - ev[sI[e] * 15 + o];
        tmp_s[idx] = d * d;
    }
    __syncthreads();
    for (int idx = tid; idx < 192; idx += 256) {
        int e = idx / 3, dg = idx - e * 3;
        int o0 = (dg == 0) ? 0 : ((dg == 1) ? 3 : 8);
        int o1 = (dg == 0) ? 3 : ((dg == 1) ? 8 : 15);
        float s = 0.f;
        for (int o = o0; o < o1; o++) s += tmp_s[e * 15 + o];
        l0_s[idx] = s;
    }
    __syncthreads();

    // ---- Phase A: hidden activations, thread t = channel a (0..223) -------
    if (tid < 224) {
        int a = tid;
        bool isr = (a < 112);
        float b0 = isr ? b1r[a] : b1s[a - 112];
        float ws0 = 0, ws1 = 0, ws2 = 0;
        if (!isr) { ws0 = w1s_s[a - 112]; ws1 = w1s_s[112 + a - 112]; ws2 = w1s_s[224 + a - 112]; }
        for (int ch = 0; ch < 4; ch++) {
            float acc[16];
#pragma unroll
            for (int e = 0; e < 16; e++) acc[e] = b0;
            if (isr) {
#pragma unroll
                for (int j4 = 0; j4 < 8; j4++) {
                    float w0 = w1r_s[(j4 * 4 + 0) * 112 + a];
                    float w1 = w1r_s[(j4 * 4 + 1) * 112 + a];
                    float w2v = w1r_s[(j4 * 4 + 2) * 112 + a];
                    float w3 = w1r_s[(j4 * 4 + 3) * 112 + a];
#pragma unroll
                    for (int e = 0; e < 16; e++) {
                        float4 r4 = *(const float4*)&rbfc_s[(ch * 16 + e) * 32 + j4 * 4];
                        acc[e] += r4.x * w0 + r4.y * w1 + r4.z * w2v + r4.w * w3;
                    }
                }
            } else {
#pragma unroll
                for (int e = 0; e < 16; e++) {
                    int ee = ch * 16 + e;
                    acc[e] += l0_s[ee * 3] * ws0 + l0_s[ee * 3 + 1] * ws1 + l0_s[ee * 3 + 2] * ws2;
                }
            }
#pragma unroll
            for (int e = 0; e < 16; e++) act_s[a * 66 + ch * 16 + e] = silu_f(acc[e]);
        }
    }
    __syncthreads();

    // ---- Phase B: w = act @ [W2r;W2s] + (b2r+b2s), edge-pair f32x2 --------
    ull acc2[4][7];
#pragma unroll
    for (int r = 0; r < 7; r++) {
        int c = tx + 32 * r;
        float b2 = b2r[c] + b2s[c];
        ull bb = fpack2(b2, b2);
#pragma unroll
        for (int ep = 0; ep < 4; ep++) acc2[ep][r] = bb;
    }
    for (int kc = 0; kc < 14; kc++) {
        for (int idx = tid; idx < 896; idx += 256) {
            int kk = idx / 56, c4 = idx - kk * 56;
            int k = kc * 16 + kk;
            const float4* src = (k < 112) ? (const float4*)&W2r[k * 224 + c4 * 4]
                                          : (const float4*)&W2s[(k - 112) * 224 + c4 * 4];
            *(float4*)&w2_s[kk * 224 + c4 * 4] = *src;
        }
        __syncthreads();
        for (int kk = 0; kk < 16; kk++) {
            int k = kc * 16 + kk;
            const ull* ap = (const ull*)&act_s[k * 66 + ty * 8];
            ull a0 = ap[0], a1 = ap[1], a2 = ap[2], a3 = ap[3];
#pragma unroll
            for (int r = 0; r < 7; r++) {
                float w = w2_s[kk * 224 + tx + 32 * r];
                ull ww = fpack2(w, w);
                ffma2(acc2[0][r], a0, ww);
                ffma2(acc2[1][r], a1, ww);
                ffma2(acc2[2][r], a2, ww);
                ffma2(acc2[3][r], a3, ww);
            }
        }
        __syncthreads();
    }

    // ---- Epilogue: alpha[e][r] = cut * sum_c w[c] * q_i[c] * k_j[c] -------
#pragma unroll
    for (int ep = 0; ep < 4; ep++) {
        int e0 = ty * 8 + 2 * ep, e1 = e0 + 1;
        int i0 = sI[e0], j0 = sJ[e0], i1 = sI[e1], j1 = sJ[e1];
#pragma unroll
        for (int r = 0; r < 7; r++) {
            int c = tx + 32 * r;
            float wlo, whi; funpack2(acc2[ep][r], wlo, whi);
            float s0 = wlo * g_q[i0 * 224 + c] * g_k[j0 * 224 + c];
            float s1 = whi * g_q[i1 * 224 + c] * g_k[j1 * 224 + c];
#pragma unroll
            for (int off = 16; off; off >>= 1) {
                s0 += __shfl_xor_sync(0xffffffffu, s0, off);
                s1 += __shfl_xor_sync(0xffffffffu, s1, off);
            }
            if (tx == 0) {
                alph_s[e0 * 7 + r] = s0 * cut_s[e0];
                alph_s[e1 * 7 + r] = s1 * cut_s[e1];
            }
        }
    }
    __syncthreads();

    // ---- Phase C: segment scatter (idx_i sorted -> few atomics) -----------
    if (tid < 224) {
        int h = tid / 56;
        int cur = sI[0]; float acc = 0.f;
        for (int e = 0; e < TILE; e++) {
            if (p0 + e >= P) break;
            int i = sI[e];
            if (i != cur) { atomicAdd(&outx[cur * 224 + tid], acc); acc = 0.f; cur = i; }
            acc += alph_s[e * 7 + h] * g_v[sJ[e] * 224 + tid];
        }
        atomicAdd(&outx[cur * 224 + tid], acc);
    } else if (tid < 239) {
        int o = tid - 224;
        int dh = (o < 3) ? 4 : ((o < 8) ? 5 : 6);
        int cur = sI[0]; float acc = 0.f;
        for (int e = 0; e < TILE; e++) {
            int p = p0 + e; if (p >= P) break;
            int i = sI[e];
            if (i != cur) { atomicAdd(&outev[cur * 15 + o], acc); acc = 0.f; cur = i; }
            acc += alph_s[e * 7 + dh] * ylm[p * 15 + o];
        }
        atomicAdd(&outev[cur * 15 + o], acc);
    }
}

// ---------------------------------------------------------------------------
extern "C" void kernel_launch(void* const* d_in, const int* in_sizes, int n_in,
                              void* d_out, int out_size) {
    const float* x    = (const float*)d_in[0];
    const float* ev   = (const float*)d_in[1];
    const float* rbf  = (const float*)d_in[2];
    const float* ylm  = (const float*)d_in[3];
    const float* cut  = (const float*)d_in[4];
    const int*   idx_i = (const int*)d_in[5];
    const int*   idx_j = (const int*)d_in[6];
    const float* W1r = (const float*)d_in[7];
    const float* b1r = (const float*)d_in[8];
    const float* W2r = (const float*)d_in[9];
    const float* b2r = (const float*)d_in[10];
    const float* W1s = (const float*)d_in[11];
    const float* b1s = (const float*)d_in[12];
    const float* W2s = (const float*)d_in[13];
    const float* b2s = (const float*)d_in[14];
    const float* Wq  = (const float*)d_in[15];
    const float* Wk  = (const float*)d_in[16];
    const float* Wv  = (const float*)d_in[17];

    int N = in_sizes[0] / 224;
    int P = in_sizes[4];
    float* outx  = (float*)d_out;
    float* outev = outx + (size_t)N * 224;

    const int NODE_SMEM = 28896 * 4;   // 115584 B
    const int EDGE_SMEM = 26128 * 4;   // 104512 B
    cudaFuncSetAttribute(k_node, cudaFuncAttributeMaxDynamicSharedMemorySize, NODE_SMEM);
    cudaFuncSetAttribute(k_edge, cudaFuncAttributeMaxDynamicSharedMemorySize, EDGE_SMEM);

    k_zero<<<2048, 256>>>(outx, N * 239);
    k_node<<<(N + BN - 1) / BN, 256, NODE_SMEM>>>(x, Wq, Wk, Wv, N);
    k_edge<<<(P + TILE - 1) / TILE, 256, EDGE_SMEM>>>(
        ev, rbf, ylm, cut, idx_i, idx_j,
        W1r, b1r, W2r, b2r, W1s, b1s, W2s, b2s, outx, outev, P);
}